// round 2
// baseline (speedup 1.0000x reference)
#include <cuda_runtime.h>
#include <cuda_bf16.h>
#include <math.h>

// NeuralNDCG, N=4096, no padding. Single persistent kernel.
//
// Math: Sinkhorn scalings are diagonal, so mat_t = diag(R_t) U diag(C_t) with
// U = exp(c_i*p_j - B_j - m_i) FIXED (bf16, 32MB, L2-resident, read-only after
// build; softmax 1/Z folded into R_0). Per iteration:
//   Cn_j = C_j / max(C_j * a_j, eps)          (a_j = colsums with current R)
//   b_i  = sum_j U_ij Cn_j  -> Rn_i = R_i / max(R_i*b_i, eps)
//   a'_j = sum_i Rn_i U_ij   (re-read of block's 128KB half-slab from L1)
// One 32MB L2 sweep + one L1 sweep + 1 grid barrier per iteration.

#define NNV 4096
#define NBLK 128
#define TPB 512
#define ROWS_PB 32          // NNV / NBLK
#define HALF_ROWS 16
#define EPSF 1e-10f
#define ITERS 50

__device__ __nv_bfloat16 g_mat[(size_t)NNV * NNV];   // 32 MB
__device__ float g_Bv[NNV];
__device__ float g_Rb[2][NNV];
__device__ float g_Cb[2][NNV];
__device__ float g_av[3][NNV];
__device__ float g_rowdcg[NNV];
__device__ float g_idcgPart[8];
__device__ unsigned g_barCnt;
__device__ unsigned g_barGen;

__device__ __forceinline__ void grid_barrier() {
    __syncthreads();
    if (threadIdx.x == 0) {
        __threadfence();
        unsigned g = *((volatile unsigned*)&g_barGen);
        if (atomicAdd(&g_barCnt, 1u) == NBLK - 1) {
            atomicExch(&g_barCnt, 0u);
            __threadfence();
            atomicAdd(&g_barGen, 1u);
        } else {
            while (*((volatile unsigned*)&g_barGen) == g) __nanosleep(64);
        }
        __threadfence();
    }
    __syncthreads();
}

__device__ __forceinline__ float wredsum(float v) {
    #pragma unroll
    for (int o = 16; o > 0; o >>= 1) v += __shfl_xor_sync(0xffffffffu, v, o);
    return v;
}
__device__ __forceinline__ float wredmax(float v) {
    #pragma unroll
    for (int o = 16; o > 0; o >>= 1) v = fmaxf(v, __shfl_xor_sync(0xffffffffu, v, o));
    return v;
}

__device__ __forceinline__ void unpack8(uint4 q, float* v) {
    const __nv_bfloat162* h = reinterpret_cast<const __nv_bfloat162*>(&q);
    #pragma unroll
    for (int p = 0; p < 4; p++) {
        float2 f = __bfloat1622float2(h[p]);
        v[2 * p] = f.x; v[2 * p + 1] = f.y;
    }
}

__global__ void __launch_bounds__(TPB, 1)
ndcg_kernel(const float* __restrict__ pred, const float* __restrict__ target,
            float* __restrict__ out)
{
    __shared__ float sA[NNV];              // p / cs (C')
    __shared__ float sB[NNV];              // B / gains*C'
    __shared__ float s_pb[HALF_ROWS][17];
    __shared__ float s_pd[HALF_ROWS][17];
    __shared__ float s_rn[HALF_ROWS];
    __shared__ float s_red[16];

    const int tid = threadIdx.x, bid = blockIdx.x;
    const int wid = tid >> 5, lane = tid & 31;

    // ================= INIT =================
    {
        int g = bid * TPB + tid;
        if (g < NNV)            g_av[0][g] = 0.0f;
        else if (g < 2 * NNV)   g_av[1][g - NNV] = 0.0f;
        else if (g < 3 * NNV)   g_Cb[0][g - 2 * NNV] = 1.0f;
    }
    if (bid < 8) {
        for (int k = tid; k < NNV; k += TPB) sA[k] = pred[k];
        __syncthreads();
        int j = bid * TPB + tid;
        float pj = sA[j], acc = 0.0f;
        #pragma unroll 8
        for (int k = 0; k < NNV; k++) acc += fabsf(pj - sA[k]);
        g_Bv[j] = acc;
    } else if (bid < 16) {
        for (int k = tid; k < NNV; k += TPB) sA[k] = target[k];
        __syncthreads();
        int j = (bid - 8) * TPB + tid;
        float tj = sA[j];
        int rank = 0;
        #pragma unroll 8
        for (int k = 0; k < NNV; k++) rank += (sA[k] > tj);
        float contrib = (exp2f(tj) - 1.0f) / log2f((float)rank + 2.0f);
        contrib = wredsum(contrib);
        if (lane == 0) s_red[wid] = contrib;
        __syncthreads();
        if (tid == 0) {
            float s = 0.0f;
            for (int k = 0; k < 16; k++) s += s_red[k];
            g_idcgPart[bid - 8] = s;
        }
    }
    grid_barrier();

    // ================= BUILD U (bf16) + R0 = 1/Z =================
    for (int k = tid; k < NNV; k += TPB) { sA[k] = pred[k]; sB[k] = __ldcg(&g_Bv[k]); }
    __syncthreads();
    {
        int gw = bid * 16 + wid;          // 2048 warps, 2 rows each
        #pragma unroll
        for (int rr = 0; rr < 2; rr++) {
            int i = gw * 2 + rr;
            float ci = (float)(NNV - 1 - 2 * i);
            float m = -INFINITY;
            for (int c = 0; c < 16; c++) {
                int j0 = (c * 32 + lane) * 8;
                #pragma unroll
                for (int mm = 0; mm < 8; mm++) {
                    float L = fmaf(ci, sA[j0 + mm], -sB[j0 + mm]);
                    m = fmaxf(m, L);
                }
            }
            m = wredmax(m);
            float z = 0.0f;
            uint4* rq = reinterpret_cast<uint4*>(g_mat + (size_t)i * NNV);
            for (int c = 0; c < 16; c++) {
                int j0 = (c * 32 + lane) * 8;
                float e[8];
                #pragma unroll
                for (int mm = 0; mm < 8; mm++) {
                    float L = fmaf(ci, sA[j0 + mm], -sB[j0 + mm]);
                    e[mm] = __expf(L - m);
                    z += e[mm];
                }
                uint4 q;
                __nv_bfloat162* hq = reinterpret_cast<__nv_bfloat162*>(&q);
                hq[0] = __floats2bfloat162_rn(e[0], e[1]);
                hq[1] = __floats2bfloat162_rn(e[2], e[3]);
                hq[2] = __floats2bfloat162_rn(e[4], e[5]);
                hq[3] = __floats2bfloat162_rn(e[6], e[7]);
                rq[c * 32 + lane] = q;
            }
            z = wredsum(z);
            if (lane == 0) g_Rb[0][i] = 1.0f / z;
        }
    }
    grid_barrier();

    // ================= BOOTSTRAP a[0] = U^T R0 =================
    {
        float colacc[8];
        #pragma unroll
        for (int mm = 0; mm < 8; mm++) colacc[mm] = 0.0f;
        int base = bid * ROWS_PB;
        #pragma unroll 4
        for (int r = 0; r < ROWS_PB; r++) {
            int i = base + r;
            float Ri = __ldcg(&g_Rb[0][i]);
            uint4 q = reinterpret_cast<const uint4*>(g_mat + (size_t)i * NNV)[tid];
            float v[8]; unpack8(q, v);
            #pragma unroll
            for (int mm = 0; mm < 8; mm++) colacc[mm] = fmaf(Ri, v[mm], colacc[mm]);
        }
        #pragma unroll
        for (int mm = 0; mm < 8; mm++) atomicAdd(&g_av[0][tid * 8 + mm], colacc[mm]);
    }
    grid_barrier();

    // ================= 50 SINKHORN ITERATIONS =================
    for (int t = 0; t < ITERS; t++) {
        const bool last = (t == ITERS - 1);
        const float* a_rd  = g_av[t % 3];
        float* a_wr        = g_av[(t + 1) % 3];
        float* a_zero      = g_av[(t + 2) % 3];
        const float* C_rd  = g_Cb[t & 1];
        float* C_wr        = g_Cb[(t + 1) & 1];
        const float* R_rd  = g_Rb[t & 1];
        float* R_wr        = g_Rb[(t + 1) & 1];

        // prologue: full C' into smem; persist slice; zero slice of a(t+2)
        for (int j = tid; j < NNV; j += TPB) {
            float Cj = __ldcg(&C_rd[j]), aj = __ldcg(&a_rd[j]);
            float Cn = Cj / fmaxf(Cj * aj, EPSF);
            sA[j] = Cn;
            if (last) sB[j] = Cn * (exp2f(target[j]) - 1.0f);
        }
        if (tid < ROWS_PB) {
            int j = bid * ROWS_PB + tid;
            float Cj = __ldcg(&C_rd[j]), aj = __ldcg(&a_rd[j]);
            C_wr[j] = Cj / fmaxf(Cj * aj, EPSF);
            if (!last) a_zero[j] = 0.0f;
        }
        __syncthreads();

        float cs_r[8], gs_r[8];
        #pragma unroll
        for (int mm = 0; mm < 8; mm++) cs_r[mm] = sA[tid * 8 + mm];
        if (last) {
            #pragma unroll
            for (int mm = 0; mm < 8; mm++) gs_r[mm] = sB[tid * 8 + mm];
        }

        float colacc[8];
        #pragma unroll
        for (int mm = 0; mm < 8; mm++) colacc[mm] = 0.0f;

        #pragma unroll
        for (int h = 0; h < 2; h++) {
            int base = bid * ROWS_PB + h * HALF_ROWS;
            // pass 1: row dots (L2 read of 128KB half-slab)
            #pragma unroll 2
            for (int r = 0; r < HALF_ROWS; r++) {
                int i = base + r;
                uint4 q = reinterpret_cast<const uint4*>(g_mat + (size_t)i * NNV)[tid];
                float v[8]; unpack8(q, v);
                float pb = 0.0f;
                #pragma unroll
                for (int mm = 0; mm < 8; mm++) pb = fmaf(v[mm], cs_r[mm], pb);
                pb = wredsum(pb);
                if (lane == 0) s_pb[r][wid] = pb;
                if (last) {
                    float pd = 0.0f;
                    #pragma unroll
                    for (int mm = 0; mm < 8; mm++) pd = fmaf(v[mm], gs_r[mm], pd);
                    pd = wredsum(pd);
                    if (lane == 0) s_pd[r][wid] = pd;
                }
            }
            __syncthreads();
            // finalize rows: b_i -> R_new (or rowdcg at last iter)
            if (tid < HALF_ROWS) {
                int i = base + tid;
                float b = 0.0f;
                #pragma unroll
                for (int k = 0; k < 16; k++) b += s_pb[tid][k];
                float Ro = __ldcg(&R_rd[i]);
                float Rn = Ro / fmaxf(Ro * b, EPSF);
                if (!last) { R_wr[i] = Rn; s_rn[tid] = Rn; }
                else {
                    float d = 0.0f;
                    #pragma unroll
                    for (int k = 0; k < 16; k++) d += s_pd[tid][k];
                    g_rowdcg[i] = Rn * d * (1.0f / log2f((float)i + 2.0f));
                }
            }
            __syncthreads();
            // pass 2: next colsums with R_new (L1 re-read of same half-slab)
            if (!last) {
                #pragma unroll 2
                for (int r = 0; r < HALF_ROWS; r++) {
                    int i = base + r;
                    float Rn = s_rn[r];
                    uint4 q = reinterpret_cast<const uint4*>(g_mat + (size_t)i * NNV)[tid];
                    float v[8]; unpack8(q, v);
                    #pragma unroll
                    for (int mm = 0; mm < 8; mm++) colacc[mm] = fmaf(Rn, v[mm], colacc[mm]);
                }
            }
        }
        if (!last) {
            #pragma unroll
            for (int mm = 0; mm < 8; mm++) atomicAdd(&a_wr[tid * 8 + mm], colacc[mm]);
        }
        grid_barrier();
    }

    // ================= FINAL =================
    if (bid == 0) {
        float part = 0.0f;
        #pragma unroll
        for (int k = 0; k < 8; k++) part += __ldcg(&g_rowdcg[tid * 8 + k]);
        part = wredsum(part);
        if (lane == 0) s_red[wid] = part;
        __syncthreads();
        if (tid == 0) {
            float dcg = 0.0f;
            for (int k = 0; k < 16; k++) dcg += s_red[k];
            float idcg = 0.0f;
            for (int k = 0; k < 8; k++) idcg += __ldcg(&g_idcgPart[k]);
            out[0] = -(dcg / (idcg + 1e-8f));
        }
    }
}

extern "C" void kernel_launch(void* const* d_in, const int* in_sizes, int n_in,
                              void* d_out, int out_size) {
    const float* pred   = (const float*)d_in[0];
    const float* target = (const float*)d_in[1];
    float* out = (float*)d_out;
    ndcg_kernel<<<NBLK, TPB>>>(pred, target, out);
}

// round 3
// speedup vs baseline: 1.3435x; 1.3435x over previous
#include <cuda_runtime.h>
#include <cuda_bf16.h>
#include <math.h>

// NeuralNDCG, N=4096. Persistent kernel, 128 blocks x 512 threads.
// mat_t = diag(R) U diag(C), U = exp(c_i p_j - B_j - m_i) fixed in bf16 (32MB,
// L2-resident read-only). Per iteration: one L2 sweep (row dots b_i) + one L1
// re-read (next colsums with fresh R) + one grid barrier. Thread t owns
// j=8t..8t+7 in every sweep, so C'/gains live in registers (no smem in the
// hot loops); per-row sums via register partials + one batched transpose.

#define NNV 4096
#define NBLK 128
#define TPB 512
#define ROWS_PB 32
#define HALF 16
#define EPSF 1e-10f
#define ITERS 50

__device__ __nv_bfloat16 g_mat[(size_t)NNV * NNV];   // 32 MB
__device__ float g_Bv[NNV];
__device__ float g_Rb[2][NNV];
__device__ float g_Cb[2][NNV];
__device__ float g_av[3][NNV];
__device__ float g_rowdcg[NNV];
__device__ float g_idcgPart[64];
__device__ unsigned g_barCnt, g_barGen;

__device__ __forceinline__ void grid_barrier() {
    __syncthreads();
    if (threadIdx.x == 0) {
        __threadfence();
        unsigned g = *((volatile unsigned*)&g_barGen);
        if (atomicAdd(&g_barCnt, 1u) == NBLK - 1) {
            atomicExch(&g_barCnt, 0u);
            __threadfence();
            atomicAdd(&g_barGen, 1u);
        } else {
            while (*((volatile unsigned*)&g_barGen) == g) __nanosleep(32);
        }
        __threadfence();
    }
    __syncthreads();
}

__device__ __forceinline__ float wredsum(float v) {
    #pragma unroll
    for (int o = 16; o > 0; o >>= 1) v += __shfl_xor_sync(0xffffffffu, v, o);
    return v;
}
__device__ __forceinline__ float wredmax(float v) {
    #pragma unroll
    for (int o = 16; o > 0; o >>= 1) v = fmaxf(v, __shfl_xor_sync(0xffffffffu, v, o));
    return v;
}
__device__ __forceinline__ float red8(float v) {   // sum over aligned 8-lane group
    #pragma unroll
    for (int o = 4; o > 0; o >>= 1) v += __shfl_xor_sync(0xffffffffu, v, o);
    return v;
}
__device__ __forceinline__ void unpack8(uint4 q, float* v) {
    const __nv_bfloat162* h = reinterpret_cast<const __nv_bfloat162*>(&q);
    #pragma unroll
    for (int p = 0; p < 4; p++) {
        float2 f = __bfloat1622float2(h[p]);
        v[2 * p] = f.x; v[2 * p + 1] = f.y;
    }
}

__global__ void __launch_bounds__(TPB, 1)
ndcg_kernel(const float* __restrict__ pred, const float* __restrict__ target,
            float* __restrict__ out)
{
    __shared__ float s_mem[HALF * TPB];   // 32KB: pb transpose / init staging
    __shared__ float s_rn[HALF];
    __shared__ float s_b[HALF];
    __shared__ float s_red[16];

    const int tid = threadIdx.x, bid = blockIdx.x;
    const int wid = tid >> 5, lane = tid & 31;

    // ================= INIT =================
    {
        int g = bid * TPB + tid;
        if (g < NNV)            g_av[0][g] = 0.0f;
        else if (g < 2 * NNV)   g_av[1][g - NNV] = 0.0f;
        else if (g < 3 * NNV)   g_Cb[0][g - 2 * NNV] = 1.0f;
    }
    if (bid < 64) {
        // B[j] = sum_k |p_j - p_k| ; 64 j per block, 8 threads per j
        for (int k = tid; k < NNV; k += TPB) s_mem[k] = pred[k];
        __syncthreads();
        int j = bid * 64 + (tid >> 3);
        int k0 = (tid & 7) * 512;
        float pj = s_mem[j], acc = 0.0f;
        #pragma unroll 8
        for (int k = 0; k < 512; k++) acc += fabsf(pj - s_mem[k0 + k]);
        acc = red8(acc);
        if ((tid & 7) == 0) g_Bv[j] = acc;
    } else {
        // ideal DCG via rank counting
        for (int k = tid; k < NNV; k += TPB) s_mem[k] = target[k];
        __syncthreads();
        int j = (bid - 64) * 64 + (tid >> 3);
        int k0 = (tid & 7) * 512;
        float tj = s_mem[j];
        int rank = 0;
        #pragma unroll 8
        for (int k = 0; k < 512; k++) rank += (s_mem[k0 + k] > tj);
        #pragma unroll
        for (int o = 4; o > 0; o >>= 1) rank += __shfl_xor_sync(0xffffffffu, rank, o);
        float contrib = ((tid & 7) == 0)
            ? (exp2f(tj) - 1.0f) / log2f((float)rank + 2.0f) : 0.0f;
        contrib = wredsum(contrib);
        if (lane == 0) s_red[wid] = contrib;
        __syncthreads();
        if (tid == 0) {
            float s = 0.0f;
            for (int k = 0; k < 16; k++) s += s_red[k];
            g_idcgPart[bid - 64] = s;
        }
    }
    grid_barrier();

    // ================= BUILD U (bf16), R0 = 1/Z =================
    {
        float* p_s = s_mem;
        float* B_s = s_mem + NNV;
        for (int k = tid; k < NNV; k += TPB) { p_s[k] = pred[k]; B_s[k] = __ldcg(&g_Bv[k]); }
        __syncthreads();
        #pragma unroll
        for (int rr = 0; rr < 2; rr++) {
            int i = bid * ROWS_PB + rr * 16 + wid;
            float ci = (float)(NNV - 1 - 2 * i);
            float m = -INFINITY;
            for (int c = 0; c < 16; c++) {
                int j0 = (c * 32 + lane) * 8;
                #pragma unroll
                for (int mm = 0; mm < 8; mm++)
                    m = fmaxf(m, fmaf(ci, p_s[j0 + mm], -B_s[j0 + mm]));
            }
            m = wredmax(m);
            float z = 0.0f;
            uint4* rq = reinterpret_cast<uint4*>(g_mat + (size_t)i * NNV);
            for (int c = 0; c < 16; c++) {
                int j0 = (c * 32 + lane) * 8;
                float e[8];
                #pragma unroll
                for (int mm = 0; mm < 8; mm++) {
                    e[mm] = __expf(fmaf(ci, p_s[j0 + mm], -B_s[j0 + mm]) - m);
                    z += e[mm];
                }
                uint4 q;
                __nv_bfloat162* hq = reinterpret_cast<__nv_bfloat162*>(&q);
                hq[0] = __floats2bfloat162_rn(e[0], e[1]);
                hq[1] = __floats2bfloat162_rn(e[2], e[3]);
                hq[2] = __floats2bfloat162_rn(e[4], e[5]);
                hq[3] = __floats2bfloat162_rn(e[6], e[7]);
                rq[c * 32 + lane] = q;
            }
            z = wredsum(z);
            if (lane == 0) g_Rb[0][i] = 1.0f / z;
        }
    }
    grid_barrier();

    // ================= BOOTSTRAP a0 = U^T R0 =================
    {
        float colacc[8];
        #pragma unroll
        for (int mm = 0; mm < 8; mm++) colacc[mm] = 0.0f;
        #pragma unroll 4
        for (int r = 0; r < ROWS_PB; r++) {
            int i = bid * ROWS_PB + r;
            float Ri = __ldcg(&g_Rb[0][i]);
            uint4 q = reinterpret_cast<const uint4*>(g_mat + (size_t)i * NNV)[tid];
            float v[8]; unpack8(q, v);
            #pragma unroll
            for (int mm = 0; mm < 8; mm++) colacc[mm] = fmaf(Ri, v[mm], colacc[mm]);
        }
        #pragma unroll
        for (int mm = 0; mm < 8; mm++) atomicAdd(&g_av[0][tid * 8 + mm], colacc[mm]);
    }
    grid_barrier();

    // ================= SINKHORN =================
    for (int t = 0; t < ITERS; t++) {
        const bool last = (t == ITERS - 1);
        const float* a_rd = g_av[t % 3];
        float* a_wr       = g_av[(t + 1) % 3];
        float* a_zero     = g_av[(t + 2) % 3];
        const float* C_rd = g_Cb[t & 1];
        float* C_wr       = g_Cb[(t + 1) & 1];
        const float* R_rd = g_Rb[t & 1];
        float* R_wr       = g_Rb[(t + 1) & 1];

        // --- prologue: C' for my 8 columns, into registers ---
        float cs_r[8];
        {
            const float4* cp = reinterpret_cast<const float4*>(C_rd + tid * 8);
            const float4* ap = reinterpret_cast<const float4*>(a_rd + tid * 8);
            float4 c0 = __ldcg(cp), c1 = __ldcg(cp + 1);
            float4 a0 = __ldcg(ap), a1 = __ldcg(ap + 1);
            cs_r[0] = c0.x / fmaxf(c0.x * a0.x, EPSF);
            cs_r[1] = c0.y / fmaxf(c0.y * a0.y, EPSF);
            cs_r[2] = c0.z / fmaxf(c0.z * a0.z, EPSF);
            cs_r[3] = c0.w / fmaxf(c0.w * a0.w, EPSF);
            cs_r[4] = c1.x / fmaxf(c1.x * a1.x, EPSF);
            cs_r[5] = c1.y / fmaxf(c1.y * a1.y, EPSF);
            cs_r[6] = c1.z / fmaxf(c1.z * a1.z, EPSF);
            cs_r[7] = c1.w / fmaxf(c1.w * a1.w, EPSF);
        }
        if (tid < ROWS_PB) {
            int j = bid * ROWS_PB + tid;
            float Cj = __ldcg(&C_rd[j]), aj = __ldcg(&a_rd[j]);
            C_wr[j] = Cj / fmaxf(Cj * aj, EPSF);
            if (!last) a_zero[j] = 0.0f;
        }

        if (!last) {
            float colacc[8];
            #pragma unroll
            for (int mm = 0; mm < 8; mm++) colacc[mm] = 0.0f;

            #pragma unroll
            for (int h = 0; h < 2; h++) {
                const int base = bid * ROWS_PB + h * HALF;
                // pass 1: 16 per-row dot partials in registers (L2 sweep)
                float pb[HALF];
                #pragma unroll
                for (int r = 0; r < HALF; r++) {
                    uint4 q = reinterpret_cast<const uint4*>(g_mat + (size_t)(base + r) * NNV)[tid];
                    float v[8]; unpack8(q, v);
                    float d = 0.0f;
                    #pragma unroll
                    for (int mm = 0; mm < 8; mm++) d = fmaf(v[mm], cs_r[mm], d);
                    pb[r] = d;
                }
                // batched transpose + warp-per-row reduce
                #pragma unroll
                for (int r = 0; r < HALF; r++) s_mem[r * TPB + tid] = pb[r];
                __syncthreads();
                {
                    float v = 0.0f;
                    #pragma unroll
                    for (int k = 0; k < 16; k++) v += s_mem[wid * TPB + lane + 32 * k];
                    v = wredsum(v);
                    if (lane == 0) {
                        int i = base + wid;
                        float Ro = __ldcg(&R_rd[i]);
                        float Rn = Ro / fmaxf(Ro * v, EPSF);
                        R_wr[i] = Rn;
                        s_rn[wid] = Rn;
                    }
                }
                __syncthreads();
                // pass 2: colsum accumulation with fresh R (L1 re-read)
                #pragma unroll
                for (int r = 0; r < HALF; r++) {
                    uint4 q = reinterpret_cast<const uint4*>(g_mat + (size_t)(base + r) * NNV)[tid];
                    float v[8]; unpack8(q, v);
                    float Rn = s_rn[r];
                    #pragma unroll
                    for (int mm = 0; mm < 8; mm++) colacc[mm] = fmaf(Rn, v[mm], colacc[mm]);
                }
                __syncthreads();   // protect s_mem for next half
            }
            #pragma unroll
            for (int mm = 0; mm < 8; mm++)
                atomicAdd(&a_wr[tid * 8 + mm], colacc[mm]);
        } else {
            // last iteration: fold DCG contraction, no matrix write/colsums
            float gs_r[8];
            #pragma unroll
            for (int mm = 0; mm < 8; mm++)
                gs_r[mm] = cs_r[mm] * (exp2f(target[tid * 8 + mm]) - 1.0f);

            #pragma unroll
            for (int h = 0; h < 2; h++) {
                const int base = bid * ROWS_PB + h * HALF;
                float pb[HALF], pd[HALF];
                #pragma unroll
                for (int r = 0; r < HALF; r++) {
                    uint4 q = reinterpret_cast<const uint4*>(g_mat + (size_t)(base + r) * NNV)[tid];
                    float v[8]; unpack8(q, v);
                    float d1 = 0.0f, d2 = 0.0f;
                    #pragma unroll
                    for (int mm = 0; mm < 8; mm++) {
                        d1 = fmaf(v[mm], cs_r[mm], d1);
                        d2 = fmaf(v[mm], gs_r[mm], d2);
                    }
                    pb[r] = d1; pd[r] = d2;
                }
                #pragma unroll
                for (int r = 0; r < HALF; r++) s_mem[r * TPB + tid] = pb[r];
                __syncthreads();
                {
                    float v = 0.0f;
                    #pragma unroll
                    for (int k = 0; k < 16; k++) v += s_mem[wid * TPB + lane + 32 * k];
                    v = wredsum(v);
                    if (lane == 0) s_b[wid] = v;
                }
                __syncthreads();
                #pragma unroll
                for (int r = 0; r < HALF; r++) s_mem[r * TPB + tid] = pd[r];
                __syncthreads();
                {
                    float v = 0.0f;
                    #pragma unroll
                    for (int k = 0; k < 16; k++) v += s_mem[wid * TPB + lane + 32 * k];
                    v = wredsum(v);
                    if (lane == 0) {
                        int i = base + wid;
                        float Ro = __ldcg(&R_rd[i]);
                        float Rn = Ro / fmaxf(Ro * s_b[wid], EPSF);
                        g_rowdcg[i] = Rn * v / log2f((float)i + 2.0f);
                    }
                }
                __syncthreads();
            }
        }
        grid_barrier();
    }

    // ================= FINAL =================
    if (bid == 0) {
        float part = 0.0f;
        #pragma unroll
        for (int k = 0; k < 8; k++) part += __ldcg(&g_rowdcg[tid * 8 + k]);
        part = wredsum(part);
        if (lane == 0) s_red[wid] = part;
        __syncthreads();
        if (tid == 0) {
            float dcg = 0.0f;
            for (int k = 0; k < 16; k++) dcg += s_red[k];
            float idcg = 0.0f;
            for (int k = 0; k < 64; k++) idcg += __ldcg(&g_idcgPart[k]);
            out[0] = -(dcg / (idcg + 1e-8f));
        }
    }
}

extern "C" void kernel_launch(void* const* d_in, const int* in_sizes, int n_in,
                              void* d_out, int out_size) {
    const float* pred   = (const float*)d_in[0];
    const float* target = (const float*)d_in[1];
    float* out = (float*)d_out;
    ndcg_kernel<<<NBLK, TPB>>>(pred, target, out);
}